// round 13
// baseline (speedup 1.0000x reference)
#include <cuda_runtime.h>

#define B_ 512
#define S_ 512
#define T_ 128
#define END_ID 1
#define L2E 1.4426950408889634f
#define LN2 0.6931471805599453f
#define NCTA 296
#define SAPAD 72   // word offset of half1 inside an sa row (64 data + 8 pad)

__device__ float g_diff[B_];
__device__ int g_next = 0;
__device__ int g_done = 0;

static __device__ __forceinline__ float ex2(float x) {
    float r; asm("ex2.approx.f32 %0, %1;" : "=f"(r) : "f"(x)); return r;
}
static __device__ __forceinline__ float lg2(float x) {
    float r; asm("lg2.approx.f32 %0, %1;" : "=f"(r) : "f"(x)); return r;
}
static __device__ __forceinline__ unsigned long long pack2(float lo, float hi) {
    unsigned long long r;
    asm("mov.b64 %0, {%1, %2};" : "=l"(r) : "r"(__float_as_uint(lo)), "r"(__float_as_uint(hi)));
    return r;
}
static __device__ __forceinline__ float hsum2(unsigned long long v) {
    unsigned int a, b;
    asm("mov.b64 {%0, %1}, %2;" : "=r"(a), "=r"(b) : "l"(v));
    return __uint_as_float(a) + __uint_as_float(b);
}
#define FMA2(acc, e, a) asm("fma.rn.f32x2 %0, %1, %2, %0;" : "+l"(acc) : "l"(e), "l"(a))
#define ADD2(o, a, b)   asm("add.rn.f32x2 %0, %1, %2;" : "=l"(o) : "l"(a), "l"(b))

static __device__ __forceinline__ float warp_sum(float v) {
#pragma unroll
    for (int o = 16; o; o >>= 1) v += __shfl_xor_sync(0xffffffffu, v, o);
    return v;
}

// 256 threads. Warp w owns tags [w*16, w*16+16); lane = 2*(tag&15)+h, h=lane&1.
// TWO independent chains per CTA, alternated per interval: a chain's
// publish->consume spans 2 barriers, so intervals are issue-bound, not
// dependency-bound. Linear-space recurrence w/ exact 2^-k renorm (no MUFU on
// the chain). Work-stealing refill per slot. 2 CTAs/SM.
__global__ void __launch_bounds__(256, 2) crf_kernel(
    const float* __restrict__ x,      // [B,S,T]
    const int*   __restrict__ tags,   // [B,S]
    const float* __restrict__ mask,   // [B,S]
    const float* __restrict__ trans,  // [T,T]
    float* __restrict__ out)
{
    const int tid  = threadIdx.x;
    const int lane = tid & 31;
    const int w    = tid >> 5;          // 8 warps
    const int h    = lane & 1;          // half (adjacent lanes share a tag)
    const int tag  = w * 16 + (lane >> 1);

    __shared__ __align__(16) float saA[2][136];
    __shared__ __align__(16) float saB[2][136];
    __shared__ float s_red[8];
    __shared__ int   s_b;
    __shared__ int   s_last;

    const int saw = (tag < 64) ? tag : (tag + 8);   // padded publish slot

    // ---- E regs: exp(trans[tag, h*64 .. h*64+63]) as 32 packed f32x2 ----
    unsigned long long er[32];
    {
        const float4* tr4 = reinterpret_cast<const float4*>(trans + tag * T_ + h * 64);
#pragma unroll
        for (int j = 0; j < 16; j++) {
            float4 v = __ldg(tr4 + j);
            er[2 * j]     = pack2(ex2(v.x * L2E), ex2(v.y * L2E));
            er[2 * j + 1] = pack2(ex2(v.z * L2E), ex2(v.w * L2E));
        }
    }

    // ---- per-slot state (len: -1 = fetch needed, 0 = drained, >0 active) ----
    int bA = 0, lenA = -1, tA = 0, KA = 0;
    int bB = 0, lenB = -1, tB = 0, KB = 0;
    float naA = 0.f, naB = 0.f;
    const float* xbA = x;
    const float* xbB = x;
    float xA0 = 0.f, xA1 = 0.f, xA2 = 0.f, xA3 = 0.f;
    float xB0 = 0.f, xB1 = 0.f, xB2 = 0.f, xB3 = 0.f;

#define EPILOGUE(BB, LL, NA, KK, XB)                                         \
    {                                                                        \
        float v_ = (h == 0)                                                  \
            ? ((NA) * ex2(__ldg(trans + END_ID * T_ + tag) * L2E)) : 0.f;    \
        v_ = warp_sum(v_);                                                   \
        __syncthreads();                                                     \
        if (lane == 0) s_red[w] = v_;                                        \
        __syncthreads();                                                     \
        float tot_ = 0.f;                                                    \
        _Pragma("unroll")                                                    \
        for (int k = 0; k < 8; k++) tot_ += s_red[k];                        \
        float fwd_ = (lg2(tot_) + (float)(KK)) * LN2;                        \
        const int* tb_ = tags + (BB) * S_;                                   \
        float gs_ = 0.f;                                                     \
        for (int u = tid; u < (LL); u += 256) {                              \
            int tn_ = tb_[u + 1];                                            \
            int tc_ = tb_[u];                                                \
            gs_ += (XB)[(size_t)u * T_ + tn_] + __ldg(trans + tn_ * T_ + tc_); \
        }                                                                    \
        gs_ = warp_sum(gs_);                                                 \
        __syncthreads();                                                     \
        if (lane == 0) s_red[w] = gs_;                                       \
        __syncthreads();                                                     \
        if (tid == 0) {                                                      \
            float gt_ = 0.f;                                                 \
            _Pragma("unroll")                                                \
            for (int k = 0; k < 8; k++) gt_ += s_red[k];                     \
            gt_ += __ldg(trans + END_ID * T_ + tb_[(LL)]);                   \
            g_diff[BB] = fwd_ - gt_;                                         \
        }                                                                    \
    }

#define FETCHINIT(BV, LENV, TV, NA, KK, XBV, X0, X1, X2, X3, SA)             \
    {                                                                        \
        __syncthreads();                                                     \
        if (tid == 0) s_b = atomicAdd(&g_next, 1);                           \
        __syncthreads();                                                     \
        int nb_ = s_b;                                                       \
        if (nb_ >= B_) {                                                     \
            LENV = 0;                                                        \
        } else {                                                             \
            BV = nb_;                                                        \
            XBV = x + (size_t)nb_ * S_ * T_;                                 \
            float lm_ = mask[nb_ * S_ + tid] + mask[nb_ * S_ + tid + 256];   \
            lm_ = warp_sum(lm_);                                             \
            if (lane == 0) s_red[w] = lm_;                                   \
            if (h == 0) SA[0][saw] = (tag == 0) ? 1.f : 0.f;                 \
            __syncthreads();                                                 \
            float lt_ = 0.f;                                                 \
            _Pragma("unroll")                                                \
            for (int k = 0; k < 8; k++) lt_ += s_red[k];                     \
            LENV = (int)(lt_ + 0.5f);                                        \
            TV = 0; NA = 0.f; KK = 0;                                        \
            X0 = ex2(__ldg(XBV + (size_t)min(0, LENV - 1) * T_ + tag) * L2E);\
            X1 = ex2(__ldg(XBV + (size_t)min(1, LENV - 1) * T_ + tag) * L2E);\
            X2 = ex2(__ldg(XBV + (size_t)min(2, LENV - 1) * T_ + tag) * L2E);\
            X3 = ex2(__ldg(XBV + (size_t)min(3, LENV - 1) * T_ + tag) * L2E);\
        }                                                                    \
    }

#define STEP(SA, TV, LENV, NA, KK, XBV, X0, X1, X2, X3)                      \
    {                                                                        \
        int px_ = TV & 1;                                                    \
        int pf_ = min(TV + 4, LENV - 1);                                     \
        float nl_ = __ldg(XBV + (size_t)pf_ * T_ + tag);                     \
        float head_ = SA[px_][0];                                            \
        const ulonglong2* sp_ =                                              \
            reinterpret_cast<const ulonglong2*>(&SA[px_][h * SAPAD]);        \
        unsigned long long a0_ = 0ull, a1_ = 0ull, a2_ = 0ull, a3_ = 0ull;   \
        _Pragma("unroll")                                                    \
        for (int j = 0; j < 8; j++) {                                        \
            ulonglong2 v0_ = sp_[2 * j];                                     \
            ulonglong2 v1_ = sp_[2 * j + 1];                                 \
            FMA2(a0_, er[4 * j],     v0_.x);                                 \
            FMA2(a1_, er[4 * j + 1], v0_.y);                                 \
            FMA2(a2_, er[4 * j + 2], v1_.x);                                 \
            FMA2(a3_, er[4 * j + 3], v1_.y);                                 \
        }                                                                    \
        unsigned long long s01_, s23_, s_;                                   \
        ADD2(s01_, a0_, a1_); ADD2(s23_, a2_, a3_); ADD2(s_, s01_, s23_);    \
        float part_ = hsum2(s_);                                             \
        part_ += __shfl_xor_sync(0xffffffffu, part_, 1);                     \
        int kk_ = ((__float_as_int(head_) >> 23) & 255) - 127;               \
        KK += kk_;                                                           \
        float sc_ = __int_as_float((127 - kk_) << 23);                       \
        NA = part_ * sc_ * (X0);                                             \
        if (h == 0) SA[px_ ^ 1][saw] = NA;                                   \
        X0 = X1; X1 = X2; X2 = X3; X3 = ex2(nl_ * L2E);                      \
        TV++;                                                                \
    }

    for (;;) {
        // ---- interval for chain A ----
        if (lenA > 0 && tA >= lenA) {
            EPILOGUE(bA, lenA, naA, KA, xbA);
            lenA = -1;
        }
        if (lenA == -1) {
            FETCHINIT(bA, lenA, tA, naA, KA, xbA, xA0, xA1, xA2, xA3, saA);
        }
        if (lenA > 0) {
            STEP(saA, tA, lenA, naA, KA, xbA, xA0, xA1, xA2, xA3);
        }
        __syncthreads();

        // ---- interval for chain B ----
        if (lenB > 0 && tB >= lenB) {
            EPILOGUE(bB, lenB, naB, KB, xbB);
            lenB = -1;
        }
        if (lenB == -1) {
            FETCHINIT(bB, lenB, tB, naB, KB, xbB, xB0, xB1, xB2, xB3, saB);
        }
        if (lenB > 0) {
            STEP(saB, tB, lenB, naB, KB, xbB, xB0, xB1, xB2, xB3);
        }
        __syncthreads();

        if (lenA == 0 && lenB == 0) break;
    }
#undef STEP
#undef FETCHINIT
#undef EPILOGUE

    // ---- fused finalize: last CTA computes the mean, resets counters ----
    if (tid == 0) {
        __threadfence();
        int vd = atomicAdd(&g_done, 1);
        s_last = (vd == NCTA - 1);
    }
    __syncthreads();
    if (s_last) {
        __threadfence();
        float ts = g_diff[tid] + g_diff[tid + 256];
        ts = warp_sum(ts);
        __syncthreads();
        if (lane == 0) s_red[w] = ts;
        __syncthreads();
        if (tid == 0) {
            float total = 0.f;
#pragma unroll
            for (int k = 0; k < 8; k++) total += s_red[k];
            out[0] = total * (1.0f / B_);
            g_next = 0;
            g_done = 0;
        }
    }
}

extern "C" void kernel_launch(void* const* d_in, const int* in_sizes, int n_in,
                              void* d_out, int out_size) {
    const float* x     = (const float*)d_in[0];
    const int*   tags  = (const int*)d_in[1];
    const float* mask  = (const float*)d_in[2];
    const float* trans = (const float*)d_in[3];
    crf_kernel<<<NCTA, 256>>>(x, tags, mask, trans, (float*)d_out);
}

// round 14
// speedup vs baseline: 1.5790x; 1.5790x over previous
#include <cuda_runtime.h>

#define B_ 512
#define S_ 512
#define T_ 128
#define END_ID 1
#define L2E 1.4426950408889634f
#define LN2 0.6931471805599453f
#define PFD 4
#define NCTA 444

__device__ float g_diff[B_];
__device__ int g_next = 0;
__device__ int g_done = 0;

static __device__ __forceinline__ float ex2(float x) {
    float r; asm("ex2.approx.f32 %0, %1;" : "=f"(r) : "f"(x)); return r;
}
static __device__ __forceinline__ float lg2(float x) {
    float r; asm("lg2.approx.f32 %0, %1;" : "=f"(r) : "f"(x)); return r;
}
static __device__ __forceinline__ unsigned long long pack2(float lo, float hi) {
    unsigned long long r;
    asm("mov.b64 %0, {%1, %2};" : "=l"(r) : "r"(__float_as_uint(lo)), "r"(__float_as_uint(hi)));
    return r;
}
static __device__ __forceinline__ float hsum2(unsigned long long v) {
    unsigned int a, b;
    asm("mov.b64 {%0, %1}, %2;" : "=r"(a), "=r"(b) : "l"(v));
    return __uint_as_float(a) + __uint_as_float(b);
}
#define FMA2(acc, e, a) asm("fma.rn.f32x2 %0, %1, %2, %0;" : "+l"(acc) : "l"(e), "l"(a))
#define ADD2(o, a, b)   asm("add.rn.f32x2 %0, %1, %2;" : "=l"(o) : "l"(a), "l"(b))

static __device__ __forceinline__ float warp_sum(float v) {
#pragma unroll
    for (int o = 16; o; o >>= 1) v += __shfl_xor_sync(0xffffffffu, v, o);
    return v;
}

// 128 threads, ONE tag per thread, full 128-wide dot in registers.
// Every hot LDS is a whole-warp broadcast; no shuffle on the chain; 4-warp
// barrier. Linear-space recurrence w/ exact 2^-k renorm. 3 CTAs/SM.
__global__ void __launch_bounds__(128, 3) crf_kernel(
    const float* __restrict__ x,      // [B,S,T]
    const int*   __restrict__ tags,   // [B,S]
    const float* __restrict__ mask,   // [B,S]
    const float* __restrict__ trans,  // [T,T]
    float* __restrict__ out)
{
    const int tid  = threadIdx.x;     // == tag
    const int lane = tid & 31;
    const int w    = tid >> 5;        // 4 warps

    __shared__ __align__(16) float sa[2][T_];
    __shared__ float s_red[4];
    __shared__ int   s_b;
    __shared__ int   s_last;

    // ---- E regs: full row exp(trans[tag, :]) as 64 packed f32x2 ----
    unsigned long long er[64];
    {
        const float4* tr4 = reinterpret_cast<const float4*>(trans + tid * T_);
#pragma unroll
        for (int j = 0; j < 32; j++) {
            float4 v = __ldg(tr4 + j);
            er[2 * j]     = pack2(ex2(v.x * L2E), ex2(v.y * L2E));
            er[2 * j + 1] = pack2(ex2(v.z * L2E), ex2(v.w * L2E));
        }
    }

    // ---- persistent work-stealing over batch elements ----
    for (;;) {
        __syncthreads();
        if (tid == 0) s_b = atomicAdd(&g_next, 1);
        __syncthreads();
        const int b = s_b;
        if (b >= B_) break;

        // length = sum(mask[b,:]) (contiguous prefix); publish a0
        float lm = mask[b * S_ + tid]       + mask[b * S_ + tid + 128]
                 + mask[b * S_ + tid + 256] + mask[b * S_ + tid + 384];
        lm = warp_sum(lm);
        if (lane == 0) s_red[w] = lm;
        sa[0][tid] = (tid == 0) ? 1.f : 0.f;   // START_ID = 0
        __syncthreads();
        const int len = (int)(s_red[0] + s_red[1] + s_red[2] + s_red[3] + 0.5f);
        const float* xb = x + (size_t)b * S_ * T_;

        // x prefetch ring: stores exp2(x*log2e) (MUFU off the serial chain)
        float xr[PFD];
#pragma unroll
        for (int d = 0; d < PFD; d++)
            xr[d] = ex2(__ldg(xb + (size_t)min(d, len - 1) * T_ + tid) * L2E);

        float na = 0.f;   // current a[tag]
        int   K  = 0;     // accumulated exact log2 renorm

#define STEP(PP, EX)                                                         \
    {                                                                        \
        __syncthreads();                                                     \
        float head_ = sa[PP][0];                                             \
        const ulonglong2* sp_ =                                              \
            reinterpret_cast<const ulonglong2*>(&sa[PP][0]);                 \
        unsigned long long a0_ = 0ull, a1_ = 0ull, a2_ = 0ull, a3_ = 0ull;   \
        _Pragma("unroll")                                                    \
        for (int j = 0; j < 16; j++) {                                       \
            ulonglong2 v0_ = sp_[2 * j];                                     \
            ulonglong2 v1_ = sp_[2 * j + 1];                                 \
            FMA2(a0_, er[4 * j],     v0_.x);                                 \
            FMA2(a1_, er[4 * j + 1], v0_.y);                                 \
            FMA2(a2_, er[4 * j + 2], v1_.x);                                 \
            FMA2(a3_, er[4 * j + 3], v1_.y);                                 \
        }                                                                    \
        unsigned long long s01_, s23_, s_;                                   \
        ADD2(s01_, a0_, a1_); ADD2(s23_, a2_, a3_); ADD2(s_, s01_, s23_);    \
        float part_ = hsum2(s_);                                             \
        int kk_ = ((__float_as_int(head_) >> 23) & 255) - 127;               \
        K += kk_;                                                            \
        float sc_ = __int_as_float((127 - kk_) << 23);                       \
        na = part_ * sc_ * (EX);                                             \
        sa[(PP) ^ 1][tid] = na;                                              \
    }

        int t = 0;
        const int full = (len / PFD) * PFD;
        for (; t < full; t += PFD) {
#pragma unroll
            for (int d = 0; d < PFD; d++) {
                float ex_ = xr[d];
                int pf = min(t + d + PFD, len - 1);
                xr[d] = ex2(__ldg(xb + (size_t)pf * T_ + tid) * L2E);
                STEP(d & 1, ex_);
            }
        }
#pragma unroll
        for (int d = 0; d < PFD - 1; d++) {
            if (t < len) { STEP(d & 1, xr[d]); t++; }
        }
#undef STEP

        // ---- fwd = ln2 * (lg2(sum_i a_i * exp(trans[END,i])) + K) ----
        float v = na * ex2(__ldg(trans + END_ID * T_ + tid) * L2E);
        v = warp_sum(v);
        __syncthreads();
        if (lane == 0) s_red[w] = v;
        __syncthreads();
        float fwd = (lg2(s_red[0] + s_red[1] + s_red[2] + s_red[3]) + (float)K) * LN2;

        // ---- gold path score ----
        const int* tb = tags + b * S_;
        float gs = 0.f;
        for (int u = tid; u < len; u += 128) {
            int tn = tb[u + 1];
            int tc = tb[u];
            gs += xb[(size_t)u * T_ + tn] + __ldg(trans + tn * T_ + tc);
        }
        gs = warp_sum(gs);
        __syncthreads();
        if (lane == 0) s_red[w] = gs;
        __syncthreads();
        if (tid == 0) {
            float gtot = s_red[0] + s_red[1] + s_red[2] + s_red[3];
            gtot += __ldg(trans + END_ID * T_ + tb[len]);
            g_diff[b] = fwd - gtot;
        }
    }

    // ---- fused finalize: last CTA computes the mean, resets counters ----
    if (tid == 0) {
        __threadfence();
        int vd = atomicAdd(&g_done, 1);
        s_last = (vd == NCTA - 1);
    }
    __syncthreads();
    if (s_last) {
        __threadfence();
        float ts = g_diff[tid]       + g_diff[tid + 128]
                 + g_diff[tid + 256] + g_diff[tid + 384];
        ts = warp_sum(ts);
        __syncthreads();
        if (lane == 0) s_red[w] = ts;
        __syncthreads();
        if (tid == 0) {
            out[0] = (s_red[0] + s_red[1] + s_red[2] + s_red[3]) * (1.0f / B_);
            g_next = 0;
            g_done = 0;
        }
    }
}

extern "C" void kernel_launch(void* const* d_in, const int* in_sizes, int n_in,
                              void* d_out, int out_size) {
    const float* x     = (const float*)d_in[0];
    const int*   tags  = (const int*)d_in[1];
    const float* mask  = (const float*)d_in[2];
    const float* trans = (const float*)d_in[3];
    crf_kernel<<<NCTA, 128>>>(x, tags, mask, trans, (float*)d_out);
}

// round 16
// speedup vs baseline: 2.0618x; 1.3058x over previous
#include <cuda_runtime.h>
#include <cuda_bf16.h>

#define B_ 512
#define S_ 512
#define T_ 128
#define END_ID 1
#define L2E 1.4426950408889634f
#define LN2 0.6931471805599453f
#define PFD 4
#define NCTA 592

__device__ float g_diff[B_];
__device__ int g_next = 0;
__device__ int g_done = 0;

static __device__ __forceinline__ float ex2(float x) {
    float r; asm("ex2.approx.f32 %0, %1;" : "=f"(r) : "f"(x)); return r;
}
static __device__ __forceinline__ float lg2(float x) {
    float r; asm("lg2.approx.f32 %0, %1;" : "=f"(r) : "f"(x)); return r;
}
static __device__ __forceinline__ __nv_bfloat162 u2b2(unsigned int u) {
    __nv_bfloat162 h;
    *reinterpret_cast<unsigned int*>(&h) = u;
    return h;
}
static __device__ __forceinline__ float warp_sum(float v) {
#pragma unroll
    for (int o = 16; o; o >>= 1) v += __shfl_xor_sync(0xffffffffu, v, o);
    return v;
}

// 128 threads, ONE tag per thread, full 128-wide dot in registers.
// bf16 state: sa + E rows in bf162 -> 16 broadcast LDS.128 + 64 HFMA2.BF16
// per step, er[] = 64 regs -> 4 CTAs/SM. bf16's fp32-range exponent makes the
// linear-space recurrence overflow-proof (fp16 was not). Exact 2^-k renorm
// from bf16 exponent bits. Work-stealing over chains.
__global__ void __launch_bounds__(128, 4) crf_kernel(
    const float* __restrict__ x,      // [B,S,T]
    const int*   __restrict__ tags,   // [B,S]
    const float* __restrict__ mask,   // [B,S]
    const float* __restrict__ trans,  // [T,T]
    float* __restrict__ out)
{
    const int tid  = threadIdx.x;     // == tag
    const int lane = tid & 31;
    const int w    = tid >> 5;        // 4 warps

    __shared__ __align__(16) __nv_bfloat16 sa16[2][T_];
    __shared__ float s_red[4];
    __shared__ int   s_b;
    __shared__ int   s_last;

    // ---- E regs: full row exp(trans[tag, :]) as 64 bf16x2 ----
    __nv_bfloat162 er[64];
    {
        const float4* tr4 = reinterpret_cast<const float4*>(trans + tid * T_);
#pragma unroll
        for (int j = 0; j < 32; j++) {
            float4 v = __ldg(tr4 + j);
            er[2 * j]     = __floats2bfloat162_rn(ex2(v.x * L2E), ex2(v.y * L2E));
            er[2 * j + 1] = __floats2bfloat162_rn(ex2(v.z * L2E), ex2(v.w * L2E));
        }
    }

    // ---- persistent work-stealing over batch elements ----
    for (;;) {
        __syncthreads();
        if (tid == 0) s_b = atomicAdd(&g_next, 1);
        __syncthreads();
        const int b = s_b;
        if (b >= B_) break;

        // length = sum(mask[b,:]) (contiguous prefix); publish a0
        float lm = mask[b * S_ + tid]       + mask[b * S_ + tid + 128]
                 + mask[b * S_ + tid + 256] + mask[b * S_ + tid + 384];
        lm = warp_sum(lm);
        if (lane == 0) s_red[w] = lm;
        sa16[0][tid] = __float2bfloat16_rn((tid == 0) ? 1.f : 0.f);  // START=0
        __syncthreads();
        const int len = (int)(s_red[0] + s_red[1] + s_red[2] + s_red[3] + 0.5f);
        const float* xb = x + (size_t)b * S_ * T_;

        // x prefetch ring: stores exp2(x*log2e) (MUFU off the serial chain)
        float xr[PFD];
#pragma unroll
        for (int d = 0; d < PFD; d++)
            xr[d] = ex2(__ldg(xb + (size_t)min(d, len - 1) * T_ + tid) * L2E);

        float na = 0.f;   // current a[tag] (fp32; stored to smem as bf16)
        int   K  = 0;     // accumulated exact log2 renorm

#define STEP(PP, EX)                                                         \
    {                                                                        \
        __syncthreads();                                                     \
        unsigned short hb_ =                                                 \
            *reinterpret_cast<const unsigned short*>(&sa16[PP][0]);          \
        const uint4* sp_ = reinterpret_cast<const uint4*>(&sa16[PP][0]);     \
        __nv_bfloat162 z_ = __float2bfloat162_rn(0.f);                       \
        __nv_bfloat162 a0_ = z_, a1_ = z_, a2_ = z_, a3_ = z_;               \
        _Pragma("unroll")                                                    \
        for (int j = 0; j < 16; j++) {                                       \
            uint4 v_ = sp_[j];                                               \
            a0_ = __hfma2(er[4 * j],     u2b2(v_.x), a0_);                   \
            a1_ = __hfma2(er[4 * j + 1], u2b2(v_.y), a1_);                   \
            a2_ = __hfma2(er[4 * j + 2], u2b2(v_.z), a2_);                   \
            a3_ = __hfma2(er[4 * j + 3], u2b2(v_.w), a3_);                   \
        }                                                                    \
        __nv_bfloat162 s01_ = __hadd2(a0_, a1_);                             \
        __nv_bfloat162 s23_ = __hadd2(a2_, a3_);                             \
        __nv_bfloat162 s_   = __hadd2(s01_, s23_);                           \
        float2 f_ = __bfloat1622float2(s_);                                  \
        float part_ = f_.x + f_.y;                                           \
        int kk_ = (int)((hb_ >> 7) & 255) - 127;                             \
        K += kk_;                                                            \
        float sc_ = __int_as_float((127 - kk_) << 23);                       \
        na = part_ * sc_ * (EX);                                             \
        sa16[(PP) ^ 1][tid] = __float2bfloat16_rn(na);                       \
    }

        int t = 0;
        const int full = (len / PFD) * PFD;
        for (; t < full; t += PFD) {
#pragma unroll
            for (int d = 0; d < PFD; d++) {
                float ex_ = xr[d];
                int pf = min(t + d + PFD, len - 1);
                xr[d] = ex2(__ldg(xb + (size_t)pf * T_ + tid) * L2E);
                STEP(d & 1, ex_);
            }
        }
#pragma unroll
        for (int d = 0; d < PFD - 1; d++) {
            if (t < len) { STEP(d & 1, xr[d]); t++; }
        }
#undef STEP

        // ---- fwd = ln2 * (lg2(sum_i a_i * exp(trans[END,i])) + K) ----
        float v = na * ex2(__ldg(trans + END_ID * T_ + tid) * L2E);
        v = warp_sum(v);
        __syncthreads();
        if (lane == 0) s_red[w] = v;
        __syncthreads();
        float fwd = (lg2(s_red[0] + s_red[1] + s_red[2] + s_red[3]) + (float)K) * LN2;

        // ---- gold path score ----
        const int* tb = tags + b * S_;
        float gs = 0.f;
        for (int u = tid; u < len; u += 128) {
            int tn = tb[u + 1];
            int tc = tb[u];
            gs += xb[(size_t)u * T_ + tn] + __ldg(trans + tn * T_ + tc);
        }
        gs = warp_sum(gs);
        __syncthreads();
        if (lane == 0) s_red[w] = gs;
        __syncthreads();
        if (tid == 0) {
            float gtot = s_red[0] + s_red[1] + s_red[2] + s_red[3];
            gtot += __ldg(trans + END_ID * T_ + tb[len]);
            g_diff[b] = fwd - gtot;
        }
    }

    // ---- fused finalize: last CTA computes the mean, resets counters ----
    if (tid == 0) {
        __threadfence();
        int vd = atomicAdd(&g_done, 1);
        s_last = (vd == NCTA - 1);
    }
    __syncthreads();
    if (s_last) {
        __threadfence();
        float ts = g_diff[tid]       + g_diff[tid + 128]
                 + g_diff[tid + 256] + g_diff[tid + 384];
        ts = warp_sum(ts);
        __syncthreads();
        if (lane == 0) s_red[w] = ts;
        __syncthreads();
        if (tid == 0) {
            out[0] = (s_red[0] + s_red[1] + s_red[2] + s_red[3]) * (1.0f / B_);
            g_next = 0;
            g_done = 0;
        }
    }
}

extern "C" void kernel_launch(void* const* d_in, const int* in_sizes, int n_in,
                              void* d_out, int out_size) {
    const float* x     = (const float*)d_in[0];
    const int*   tags  = (const int*)d_in[1];
    const float* mask  = (const float*)d_in[2];
    const float* trans = (const float*)d_in[3];
    crf_kernel<<<NCTA, 128>>>(x, tags, mask, trans, (float*)d_out);
}